// round 13
// baseline (speedup 1.0000x reference)
#include <cuda_runtime.h>
#include <cuda_fp16.h>
#include <cstdint>
#include <cstddef>

// Problem constants
#define NB 32
#define NT 512
#define NI 256
#define NH 512

// -------------------- device scratch (no allocations allowed) --------------------
// xp layout: [d][t][b(32)][row(2048)], row = unit*4 + gate  (gate: 0=i,1=f,2=g,3=o)
__device__ float    g_xp[2u * 512u * 32u * 2048u];   // 268 MB
// h split-fp16 double buffer: [d][parity][op(hi/lo)][b(32)][k(512)] __half
__device__ __half   g_hs[2 * 2 * 2 * 32 * 512];
// per-producer step flags: flag[d][p] at stride 32 u32. 32 producers per dir.
__device__ unsigned g_flags[2 * 32 * 32];

// -------------------- helpers --------------------
__device__ __forceinline__ float tanh_fast(float x) {
    float r;
    asm("tanh.approx.f32 %0, %1;" : "=f"(r) : "f"(x));
    return r;
}
__device__ __forceinline__ float sigmoid_t(float x) {   // 0.5 + 0.5*tanh(x/2)
    return 0.5f + 0.5f * tanh_fast(0.5f * x);
}
__device__ __forceinline__ unsigned ld_acquire_gpu(const unsigned* p) {
    unsigned v;
    asm volatile("ld.acquire.gpu.u32 %0, [%1];" : "=r"(v) : "l"(p) : "memory");
    return v;
}
__device__ __forceinline__ void st_release_gpu(unsigned* p, unsigned v) {
    asm volatile("st.release.gpu.u32 [%0], %1;" :: "l"(p), "r"(v) : "memory");
}
__device__ __forceinline__ uint32_t smem_to_u32(const void* smem_ptr) {
    uint32_t addr;
    asm("{ .reg .u64 tmp; cvta.to.shared.u64 tmp, %1; cvt.u32.u64 %0, tmp; }"
        : "=r"(addr) : "l"(smem_ptr));
    return addr;
}

// ldmatrix (sm_75+), mma.sync m16n8k16 f16->f32 (sm_80+), cp.async (sm_80+)
__device__ __forceinline__ void ldm_x4(uint32_t& r0, uint32_t& r1, uint32_t& r2, uint32_t& r3,
                                       uint32_t addr) {
    asm volatile("ldmatrix.sync.aligned.m8n8.x4.shared.b16 {%0,%1,%2,%3}, [%4];"
        : "=r"(r0), "=r"(r1), "=r"(r2), "=r"(r3) : "r"(addr));
}
__device__ __forceinline__ void mma16816(float* d, const uint32_t* a, const uint32_t* b) {
    asm volatile(
        "mma.sync.aligned.m16n8k16.row.col.f32.f16.f16.f32 "
        "{%0,%1,%2,%3}, {%4,%5,%6,%7}, {%8,%9}, {%0,%1,%2,%3};"
        : "+f"(d[0]), "+f"(d[1]), "+f"(d[2]), "+f"(d[3])
        : "r"(a[0]), "r"(a[1]), "r"(a[2]), "r"(a[3]), "r"(b[0]), "r"(b[1]));
}
#define CP_ASYNC16(smem_u32, gptr) \
    asm volatile("cp.async.cg.shared.global [%0], [%1], 16;" :: "r"(smem_u32), "l"(gptr))
#define CP_COMMIT()  asm volatile("cp.async.commit_group;" ::: "memory")
#define CP_WAIT0()   asm volatile("cp.async.wait_group 0;" ::: "memory")

// split a float into fp16 hi + fp16 lo
__device__ __forceinline__ void split16(float v, __half& hi, __half& lo) {
    hi = __float2half_rn(v);
    lo = __float2half_rn(v - __half2float(hi));
}

// ==================================================================================
// Phase A: HMMA input projections (3-pass split precision, proven in R11).
// xp[d][t][b][row] = sum_i x[b][t][i] * W_ih[d][wrow(row)][i] + bias, row = ju*4+g.
// CTA = (row-block 128, t-block 32, dir). Init of g_hs/g_flags fused into first 8.
// ==================================================================================
#define XROWB  528
#define XA_HI  0
#define XA_LO  (XA_HI + 128 * XROWB)
#define XB_HI  (XA_LO + 128 * XROWB)
#define XB_LO  (XB_HI + 32 * XROWB)
#define XDST   (XB_LO + 32 * XROWB)
#define XBIAS  (XDST + 16896)
#define XPROJ_SMEM (XBIAS + 640)

__global__ __launch_bounds__(256, 1) void k_xproj(
    const float* __restrict__ x,
    const float* __restrict__ Wf, const float* __restrict__ bf,
    const float* __restrict__ Wb, const float* __restrict__ bb)
{
    extern __shared__ char smem[];
    const uint32_t sb = smem_to_u32(smem);
    float* Dst   = (float*)(smem + XDST);
    float* biasS = (float*)(smem + XBIAS);

    const int d    = blockIdx.z;
    const int R0   = blockIdx.x * 128;
    const int t0   = blockIdx.y * 32;
    const int tid  = threadIdx.x;
    const int lane = tid & 31;
    const int wid  = tid >> 5;
    const float* W    = d ? Wb : Wf;
    const float* bias = d ? bb : bf;

    // ---- fused init: zero g_hs parity 0 (both dirs, hi+lo) + flags
    if (blockIdx.z == 0 && blockIdx.y == 0 && blockIdx.x < 8) {
        int t = blockIdx.x * 256 + tid;   // 0..2047
        #pragma unroll
        for (int r = 0; r < 4; r++) {
            int dd = r >> 1, op = r & 1;
            uint4* z = (uint4*)&g_hs[(((size_t)dd * 2 + 0) * 2 + op) * 32 * 512];
            z[t] = make_uint4(0, 0, 0, 0);
        }
        if (t < 2 * 32 * 32) g_flags[t] = 0u;
    }

    // ---- A stage: W rows hi/lo
    for (int idx = tid; idx < 8192; idx += 256) {
        int r  = idx >> 6;
        int i4 = idx & 63;
        int grow = R0 + r;
        int wrow = ((grow & 3) << 9) + (grow >> 2);
        float4 v = *(const float4*)(W + (size_t)wrow * 256 + i4 * 4);
        __half h0, l0, h1, l1, h2, l2, h3, l3;
        split16(v.x, h0, l0); split16(v.y, h1, l1);
        split16(v.z, h2, l2); split16(v.w, h3, l3);
        __half2 hh01 = __halves2half2(h0, h1), hh23 = __halves2half2(h2, h3);
        __half2 ll01 = __halves2half2(l0, l1), ll23 = __halves2half2(l2, l3);
        uint2 hv, lv;
        hv.x = *(uint32_t*)&hh01; hv.y = *(uint32_t*)&hh23;
        lv.x = *(uint32_t*)&ll01; lv.y = *(uint32_t*)&ll23;
        *(uint2*)(smem + XA_HI + r * XROWB + i4 * 8) = hv;
        *(uint2*)(smem + XA_LO + r * XROWB + i4 * 8) = lv;
    }
    if (tid < 128) {
        int grow = R0 + tid;
        biasS[tid] = bias[((grow & 3) << 9) + (grow >> 2)];
    }
    __syncthreads();

    const int mi = wid;
    const uint32_t a_off = (uint32_t)(mi * 16 + (lane & 15)) * XROWB + ((lane >> 4) & 1) * 16;
    const int b_row = (lane & 7) + ((lane & 16) >> 1);
    const uint32_t b_off = (uint32_t)b_row * XROWB + ((lane >> 3) & 1) * 16;

    const int b_w  = tid >> 3;
    const int rq_w = tid & 7;

    for (int tl = 0; tl < 32; tl++) {
        const int t = t0 + tl;
        __syncthreads();

        // ---- stage x[t]: [32,256] f32 -> hi/lo fp16
        #pragma unroll
        for (int j = 0; j < 8; j++) {
            int l  = tid + j * 256;
            int b  = l >> 6;
            int i4 = l & 63;
            float4 v = *(const float4*)(x + ((size_t)(b * 512 + t)) * 256 + i4 * 4);
            __half h0, l0, h1, l1, h2, l2, h3, l3;
            split16(v.x, h0, l0); split16(v.y, h1, l1);
            split16(v.z, h2, l2); split16(v.w, h3, l3);
            __half2 hh01 = __halves2half2(h0, h1), hh23 = __halves2half2(h2, h3);
            __half2 ll01 = __halves2half2(l0, l1), ll23 = __halves2half2(l2, l3);
            uint2 hv, lv;
            hv.x = *(uint32_t*)&hh01; hv.y = *(uint32_t*)&hh23;
            lv.x = *(uint32_t*)&ll01; lv.y = *(uint32_t*)&ll23;
            *(uint2*)(smem + XB_HI + b * XROWB + i4 * 8) = hv;
            *(uint2*)(smem + XB_LO + b * XROWB + i4 * 8) = lv;
        }
        __syncthreads();

        // ---- 3-pass MMA over K=256 (16 chunks)
        float accA[4][4], accB[4][4], accC[4][4];
        #pragma unroll
        for (int nt = 0; nt < 4; nt++)
            #pragma unroll
            for (int e = 0; e < 4; e++) { accA[nt][e] = 0.f; accB[nt][e] = 0.f; accC[nt][e] = 0.f; }

        {
            uint32_t aH = sb + XA_HI + a_off;
            uint32_t aL = sb + XA_LO + a_off;
            uint32_t bH0 = sb + XB_HI + b_off;
            uint32_t bH1 = bH0 + 16 * XROWB;
            uint32_t bL0 = sb + XB_LO + b_off;
            uint32_t bL1 = bL0 + 16 * XROWB;
            #pragma unroll 2
            for (int kc = 0; kc < 16; kc++) {
                uint32_t ahi[4], alo[4], bh[8], bl[8];
                ldm_x4(ahi[0], ahi[1], ahi[2], ahi[3], aH + kc * 32);
                ldm_x4(alo[0], alo[1], alo[2], alo[3], aL + kc * 32);
                ldm_x4(bh[0], bh[1], bh[2], bh[3], bH0 + kc * 32);
                ldm_x4(bh[4], bh[5], bh[6], bh[7], bH1 + kc * 32);
                ldm_x4(bl[0], bl[1], bl[2], bl[3], bL0 + kc * 32);
                ldm_x4(bl[4], bl[5], bl[6], bl[7], bL1 + kc * 32);
                #pragma unroll
                for (int nt = 0; nt < 4; nt++) {
                    mma16816(accA[nt], ahi, bh + nt * 2);
                    mma16816(accB[nt], ahi, bl + nt * 2);
                    mma16816(accC[nt], alo, bh + nt * 2);
                }
            }
        }

        // ---- dump D tile to Dst
        {
            int rw  = mi * 16 + (lane >> 2);
            int cw0 = (lane & 3) * 2;
            #pragma unroll
            for (int nt = 0; nt < 4; nt++) {
                int col = nt * 8 + cw0;
                Dst[rw * 33 + col]           = accA[nt][0] + accB[nt][0] + accC[nt][0];
                Dst[rw * 33 + col + 1]       = accA[nt][1] + accB[nt][1] + accC[nt][1];
                Dst[(rw + 8) * 33 + col]     = accA[nt][2] + accB[nt][2] + accC[nt][2];
                Dst[(rw + 8) * 33 + col + 1] = accA[nt][3] + accB[nt][3] + accC[nt][3];
            }
        }
        __syncthreads();

        // ---- write out with bias
        {
            float* op = g_xp + ((size_t)((d * 512 + t) * 32) + b_w) * 2048 + R0 + rq_w * 16;
            #pragma unroll
            for (int e = 0; e < 16; e += 4) {
                int r = rq_w * 16 + e;
                float4 o;
                o.x = Dst[(r + 0) * 33 + b_w] + biasS[r + 0];
                o.y = Dst[(r + 1) * 33 + b_w] + biasS[r + 1];
                o.z = Dst[(r + 2) * 33 + b_w] + biasS[r + 2];
                o.w = Dst[(r + 3) * 33 + b_w] + biasS[r + 3];
                *(float4*)(op + e) = o;
            }
        }
    }
}

// ==================================================================================
// Phase B: persistent recurrent kernel (v10: 32 producers/dir, M=64 per CTA).
// 64 CTAs x 256 thr, ~142KB smem, 1 CTA/SM, co-resident => spin-safe.
// CTA bid: d = bid>>5, p = bid&31 owns units j0 = p*16 (=64 gate rows, M=64).
// D[64,32] = Whi x (hhi + hlo)^T  (2-pass; W fp16 err ~1e-4, h exact hi+lo).
// Warps: mi = wid>>1 (4 m16-tiles), ni = wid&1 (n16 half = 2 n8-tiles).
// A-hi fragments preloaded to registers (32 chunks x 4 = 128 regs, W constant).
// Per warp per step: 64 B-LDSM (x4 over 2 chunks) + 128 mma.
// Staging: piece (op,b,k16) depends on producer (k16>>1) = (tid&63)>>1 -> per-lane
// flag poll + cp.async. Finalize: thread = (ju=tid&15, b0=tid>>4), batches b0,b0+16.
// ==================================================================================
#define ROWB   1040
#define B_HI   0
#define B_LO   (B_HI + 32 * ROWB)            // 33280
#define DST_O  (B_LO + 32 * ROWB)            // 66560 ; float[64*33] = 8448
#define AST_O  (DST_O + 8448)                // 75008 ; W-hi staging 64*ROWB = 66560
#define RECUR_SMEM (AST_O + 64 * ROWB)

__global__ __launch_bounds__(256, 1) void k_recur(
    const float* __restrict__ Whf,
    const float* __restrict__ Whb,
    float* __restrict__ out)
{
    extern __shared__ char smem[];
    const uint32_t sb = smem_to_u32(smem);
    float* Dst = (float*)(smem + DST_O);

    const int bid  = blockIdx.x;
    const int d    = bid >> 5;
    const int p    = bid & 31;
    const int j0   = p * 16;
    const int tid  = threadIdx.x;
    const int lane = tid & 31;
    const int wid  = tid >> 5;
    const int mi   = wid >> 1;           // 0..3  m16-tile
    const int ni   = wid & 1;            // 0..1  n16 half
    const float* Wh = d ? Whb : Whf;

    // ---- stage W-hi rows (ju*4+g, 64 rows) into AST, preload A fragments
    for (int idx = tid; idx < 64 * 512; idx += 256) {
        int row = idx >> 9;
        int k   = idx & 511;
        int ju  = row >> 2, g = row & 3;
        float wv = Wh[((size_t)(g * 512 + j0 + ju)) * 512 + k];
        *(__half*)(smem + AST_O + row * ROWB + k * 2) = __float2half_rn(wv);
    }
    __syncthreads();

    uint32_t a_frag[32][4];
    {
        const uint32_t a_off = (uint32_t)(mi * 16 + (lane & 15)) * ROWB + ((lane >> 4) & 1) * 16;
        uint32_t aH = sb + AST_O + a_off;
        #pragma unroll
        for (int kc = 0; kc < 32; kc++)
            ldm_x4(a_frag[kc][0], a_frag[kc][1], a_frag[kc][2], a_frag[kc][3], aH + kc * 32);
    }
    __syncthreads();

    unsigned* flags  = g_flags + d * 32 * 32;
    unsigned* myflag = flags + p * 32;
    __half*   hsd    = g_hs + (size_t)d * 2 * 2 * 32 * 512;   // [parity][op][b][k]

    // B x4 lane offsets for the warp's two n8-tiles (rows ni*16 + nt*8 + lane&7)
    const uint32_t b_off0 = (uint32_t)(ni * 16 + (lane & 7)) * ROWB + ((lane >> 3) & 3) * 16;
    const uint32_t b_off1 = b_off0 + 8 * ROWB;

    const int ju_f = tid & 15;
    const int b0_f = tid >> 4;           // batches b0_f and b0_f+16
    const int jg_f = j0 + ju_f;
    const int myprod = (tid & 63) >> 1;  // producer this thread's staging depends on
    float c0 = 0.0f, c1 = 0.0f;

    float4 xg0, xg1;
    {
        const int tt0 = d ? 511 : 0;
        const float* xb = g_xp + (size_t)((d * 512 + tt0) * 32) * 2048 + jg_f * 4;
        xg0 = *(const float4*)(xb + (size_t)b0_f * 2048);
        xg1 = *(const float4*)(xb + (size_t)(b0_f + 16) * 2048);
    }

    for (int s = 0; s < 512; s++) {
        const int tt = d ? (511 - s) : s;

        // ---- (0+1) per-lane gate + stage (16 pieces per thread, same producer)
        while (ld_acquire_gpu(flags + myprod * 32) < (unsigned)s) { }
        {
            const uint4* hp = (const uint4*)(hsd + (size_t)(s & 1) * 2 * 32 * 512);
            #pragma unroll
            for (int i = 0; i < 16; i++) {
                int id  = tid + i * 256;
                int op  = id >> 11;
                int b   = (id >> 6) & 31;
                int k16 = id & 63;
                uint32_t daddr = sb + (op ? B_LO : B_HI) + b * ROWB + k16 * 16;
                CP_ASYNC16(daddr, hp + id);
            }
            CP_COMMIT();
            CP_WAIT0();
        }
        __syncthreads();

        // ---- (2) HMMA: A from registers, 16 iters x (4 B-ldsm + 8 mma)
        float aH0[4] = {0.f, 0.f, 0.f, 0.f};   // n-tile 0, Whi*hhi
        float aH1[4] = {0.f, 0.f, 0.f, 0.f};   // n-tile 1, Whi*hhi
        float aL0[4] = {0.f, 0.f, 0.f, 0.f};   // n-tile 0, Whi*hlo
        float aL1[4] = {0.f, 0.f, 0.f, 0.f};   // n-tile 1, Whi*hlo
        {
            uint32_t bH0 = sb + B_HI + b_off0;
            uint32_t bH1 = sb + B_HI + b_off1;
            uint32_t bL0 = sb + B_LO + b_off0;
            uint32_t bL1 = sb + B_LO + b_off1;
            #pragma unroll 4
            for (int kc = 0; kc < 32; kc += 2) {
                uint32_t bh0[4], bh1[4], bl0[4], bl1[4];
                ldm_x4(bh0[0], bh0[1], bh0[2], bh0[3], bH0 + kc * 32);
                ldm_x4(bh1[0], bh1[1], bh1[2], bh1[3], bH1 + kc * 32);
                ldm_x4(bl0[0], bl0[1], bl0[2], bl0[3], bL0 + kc * 32);
                ldm_x4(bl1[0], bl1[1], bl1[2], bl1[3], bL1 + kc * 32);
                mma16816(aH0, a_frag[kc],     bh0);
                mma16816(aH0, a_frag[kc + 1], bh0 + 2);
                mma16816(aH1, a_frag[kc],     bh1);
                mma16816(aH1, a_frag[kc + 1], bh1 + 2);
                mma16816(aL0, a_frag[kc],     bl0);
                mma16816(aL0, a_frag[kc + 1], bl0 + 2);
                mma16816(aL1, a_frag[kc],     bl1);
                mma16816(aL1, a_frag[kc + 1], bl1 + 2);
            }
        }

        // ---- (3) dump D tile: rows mi*16 + lane/4 (+8), cols ni*16 + nt*8 + (lane%4)*2
        {
            int rw = mi * 16 + (lane >> 2);
            int cw = ni * 16 + (lane & 3) * 2;
            Dst[rw * 33 + cw]                = aH0[0] + aL0[0];
            Dst[rw * 33 + cw + 1]            = aH0[1] + aL0[1];
            Dst[(rw + 8) * 33 + cw]          = aH0[2] + aL0[2];
            Dst[(rw + 8) * 33 + cw + 1]      = aH0[3] + aL0[3];
            Dst[rw * 33 + cw + 8]            = aH1[0] + aL1[0];
            Dst[rw * 33 + cw + 9]            = aH1[1] + aL1[1];
            Dst[(rw + 8) * 33 + cw + 8]      = aH1[2] + aL1[2];
            Dst[(rw + 8) * 33 + cw + 9]      = aH1[3] + aL1[3];
        }
        __syncthreads();

        // ---- (4) finalize: thread owns unit jg_f, batches b0_f and b0_f+16
        {
            const float* db = Dst + (4 * ju_f) * 33;
            __half* hw = hsd + (size_t)((s + 1) & 1) * 2 * 32 * 512;

            float gi = sigmoid_t(db[b0_f]            + xg0.x);
            float gf = sigmoid_t(db[33 + b0_f]       + xg0.y);
            float gg = tanh_fast(db[66 + b0_f]       + xg0.z);
            float go = sigmoid_t(db[99 + b0_f]       + xg0.w);
            c0 = gf * c0 + gi * gg;
            float h0 = go * tanh_fast(c0);

            gi = sigmoid_t(db[b0_f + 16]       + xg1.x);
            gf = sigmoid_t(db[33 + b0_f + 16]  + xg1.y);
            gg = tanh_fast(db[66 + b0_f + 16]  + xg1.z);
            go = sigmoid_t(db[99 + b0_f + 16]  + xg1.w);
            c1 = gf * c1 + gi * gg;
            float h1 = go * tanh_fast(c1);

            __half hi0, lo0, hi1, lo1;
            split16(h0, hi0, lo0);
            split16(h1, hi1, lo1);
            hw[b0_f * 512 + jg_f]                 = hi0;
            hw[16384 + b0_f * 512 + jg_f]         = lo0;
            hw[(b0_f + 16) * 512 + jg_f]          = hi1;
            hw[16384 + (b0_f + 16) * 512 + jg_f]  = lo1;
            out[((size_t)b0_f * 512 + tt) * 1024 + d * 512 + jg_f]        = h0;
            out[((size_t)(b0_f + 16) * 512 + tt) * 1024 + d * 512 + jg_f] = h1;

            if (s + 1 < 512) {
                const int ttn = d ? (510 - s) : (s + 1);
                const float* xb = g_xp + (size_t)((d * 512 + ttn) * 32) * 2048 + jg_f * 4;
                xg0 = *(const float4*)(xb + (size_t)b0_f * 2048);
                xg1 = *(const float4*)(xb + (size_t)(b0_f + 16) * 2048);
            }
        }

        // ---- (5) publish
        __syncthreads();
        if (tid == 0) st_release_gpu(myflag, (unsigned)(s + 1));
    }
}

// ==================================================================================
extern "C" void kernel_launch(void* const* d_in, const int* in_sizes, int n_in,
                              void* d_out, int out_size)
{
    const float* x    = (const float*)d_in[0];
    const float* Wihf = (const float*)d_in[1];
    const float* Whhf = (const float*)d_in[2];
    const float* bf   = (const float*)d_in[3];
    const float* Wihb = (const float*)d_in[4];
    const float* Whhb = (const float*)d_in[5];
    const float* bb   = (const float*)d_in[6];
    float* out = (float*)d_out;

    cudaFuncSetAttribute(k_xproj, cudaFuncAttributeMaxDynamicSharedMemorySize, XPROJ_SMEM);
    cudaFuncSetAttribute(k_recur, cudaFuncAttributeMaxDynamicSharedMemorySize, RECUR_SMEM);

    k_xproj<<<dim3(16, 16, 2), 256, XPROJ_SMEM>>>(x, Wihf, bf, Wihb, bb);
    k_recur<<<64, 256, RECUR_SMEM>>>(Whhf, Whhb, out);
}

// round 14
// speedup vs baseline: 1.0907x; 1.0907x over previous
#include <cuda_runtime.h>
#include <cuda_fp16.h>
#include <cstdint>
#include <cstddef>

// Problem constants
#define NB 32
#define NT 512
#define NI 256
#define NH 512

// -------------------- device scratch (no allocations allowed) --------------------
// xp layout: [d][t][b(32)][row(2048)], row = unit*4 + gate  (gate: 0=i,1=f,2=g,3=o)
__device__ float    g_xp[2u * 512u * 32u * 2048u];   // 268 MB
// x pre-split fp16: [op(hi/lo)][t(512)][b(32)][i(256)]
__device__ __half   g_xh[2u * 512u * 32u * 256u];    // 16 MB
// h split-fp16 double buffer: [d][parity][op(hi/lo)][b(32)][k(512)] __half
__device__ __half   g_hs[2 * 2 * 2 * 32 * 512];
// per-producer step flags: flag[d][p] at stride 32 u32. 64 producers per dir.
__device__ unsigned g_flags[2 * 64 * 32];

// -------------------- helpers --------------------
__device__ __forceinline__ float tanh_fast(float x) {
    float r;
    asm("tanh.approx.f32 %0, %1;" : "=f"(r) : "f"(x));
    return r;
}
__device__ __forceinline__ float sigmoid_t(float x) {   // 0.5 + 0.5*tanh(x/2)
    return 0.5f + 0.5f * tanh_fast(0.5f * x);
}
__device__ __forceinline__ unsigned ld_acquire_gpu(const unsigned* p) {
    unsigned v;
    asm volatile("ld.acquire.gpu.u32 %0, [%1];" : "=r"(v) : "l"(p) : "memory");
    return v;
}
__device__ __forceinline__ void st_release_gpu(unsigned* p, unsigned v) {
    asm volatile("st.release.gpu.u32 [%0], %1;" :: "l"(p), "r"(v) : "memory");
}
__device__ __forceinline__ uint32_t smem_to_u32(const void* smem_ptr) {
    uint32_t addr;
    asm("{ .reg .u64 tmp; cvta.to.shared.u64 tmp, %1; cvt.u32.u64 %0, tmp; }"
        : "=r"(addr) : "l"(smem_ptr));
    return addr;
}

// ldmatrix (sm_75+), mma.sync m16n8k16 f16->f32 (sm_80+), cp.async (sm_80+)
__device__ __forceinline__ void ldm_x4(uint32_t& r0, uint32_t& r1, uint32_t& r2, uint32_t& r3,
                                       uint32_t addr) {
    asm volatile("ldmatrix.sync.aligned.m8n8.x4.shared.b16 {%0,%1,%2,%3}, [%4];"
        : "=r"(r0), "=r"(r1), "=r"(r2), "=r"(r3) : "r"(addr));
}
__device__ __forceinline__ void mma16816(float* d, const uint32_t* a, const uint32_t* b) {
    asm volatile(
        "mma.sync.aligned.m16n8k16.row.col.f32.f16.f16.f32 "
        "{%0,%1,%2,%3}, {%4,%5,%6,%7}, {%8,%9}, {%0,%1,%2,%3};"
        : "+f"(d[0]), "+f"(d[1]), "+f"(d[2]), "+f"(d[3])
        : "r"(a[0]), "r"(a[1]), "r"(a[2]), "r"(a[3]), "r"(b[0]), "r"(b[1]));
}
#define CP_ASYNC16(smem_u32, gptr) \
    asm volatile("cp.async.cg.shared.global [%0], [%1], 16;" :: "r"(smem_u32), "l"(gptr))
#define CP_COMMIT()  asm volatile("cp.async.commit_group;" ::: "memory")
#define CP_WAIT0()   asm volatile("cp.async.wait_group 0;" ::: "memory")

// split a float into fp16 hi + fp16 lo
__device__ __forceinline__ void split16(float v, __half& hi, __half& lo) {
    hi = __float2half_rn(v);
    lo = __float2half_rn(v - __half2float(hi));
}

// ==================================================================================
// Phase A0: one-shot x split.  g_xh[op][t][b][i] = hi/lo fp16 of x[b][t][i].
// id over [b(32)][t(512)][i4(64)] float4; x index = id*4 exactly.
// ==================================================================================
__global__ __launch_bounds__(256) void k_xsplit(const float* __restrict__ x) {
    int id = blockIdx.x * 256 + threadIdx.x;    // 0 .. 1048575
    int b   = id >> 15;
    int rem = id & 32767;
    int t   = rem >> 6;
    int i4  = rem & 63;
    float4 v = *(const float4*)(x + (size_t)id * 4);
    __half h0, l0, h1, l1, h2, l2, h3, l3;
    split16(v.x, h0, l0); split16(v.y, h1, l1);
    split16(v.z, h2, l2); split16(v.w, h3, l3);
    __half2 hh01 = __halves2half2(h0, h1), hh23 = __halves2half2(h2, h3);
    __half2 ll01 = __halves2half2(l0, l1), ll23 = __halves2half2(l2, l3);
    uint2 hv, lv;
    hv.x = *(uint32_t*)&hh01; hv.y = *(uint32_t*)&hh23;
    lv.x = *(uint32_t*)&ll01; lv.y = *(uint32_t*)&ll23;
    size_t dst = (((size_t)t * 32 + b) * 256) + i4 * 4;
    *(uint2*)(g_xh + dst)                     = hv;
    *(uint2*)(g_xh + 4194304u + dst)          = lv;   // op stride = 512*32*256
}

// ==================================================================================
// Phase A: HMMA input projections (3-pass split precision, proven in R11).
// xp[d][t][b][row] = sum_i x[b][t][i] * W_ih[d][wrow(row)][i] + bias, row = ju*4+g.
// CTA = (row-block 128, t-block 32, dir). x tiles come pre-split from g_xh via
// cp.async (no per-tile cvt work). Init of g_hs/g_flags fused into first 8 CTAs.
// ==================================================================================
#define XROWB  528
#define XA_HI  0
#define XA_LO  (XA_HI + 128 * XROWB)
#define XB_HI  (XA_LO + 128 * XROWB)
#define XB_LO  (XB_HI + 32 * XROWB)
#define XDST   (XB_LO + 32 * XROWB)
#define XBIAS  (XDST + 16896)
#define XPROJ_SMEM (XBIAS + 640)

__global__ __launch_bounds__(256, 1) void k_xproj(
    const float* __restrict__ x,
    const float* __restrict__ Wf, const float* __restrict__ bf,
    const float* __restrict__ Wb, const float* __restrict__ bb)
{
    extern __shared__ char smem[];
    const uint32_t sb = smem_to_u32(smem);
    float* Dst   = (float*)(smem + XDST);
    float* biasS = (float*)(smem + XBIAS);

    const int d    = blockIdx.z;
    const int R0   = blockIdx.x * 128;
    const int t0   = blockIdx.y * 32;
    const int tid  = threadIdx.x;
    const int lane = tid & 31;
    const int wid  = tid >> 5;
    const float* W    = d ? Wb : Wf;
    const float* bias = d ? bb : bf;

    // ---- fused init: zero g_hs parity 0 (both dirs, hi+lo) + flags
    if (blockIdx.z == 0 && blockIdx.y == 0 && blockIdx.x < 8) {
        int t = blockIdx.x * 256 + tid;   // 0..2047
        #pragma unroll
        for (int r = 0; r < 4; r++) {
            int dd = r >> 1, op = r & 1;
            uint4* z = (uint4*)&g_hs[(((size_t)dd * 2 + 0) * 2 + op) * 32 * 512];
            z[t] = make_uint4(0, 0, 0, 0);
        }
        #pragma unroll
        for (int i = 0; i < 2; i++)
            g_flags[t + i * 2048] = 0u;
    }

    // ---- A stage: W rows hi/lo
    for (int idx = tid; idx < 8192; idx += 256) {
        int r  = idx >> 6;
        int i4 = idx & 63;
        int grow = R0 + r;
        int wrow = ((grow & 3) << 9) + (grow >> 2);
        float4 v = *(const float4*)(W + (size_t)wrow * 256 + i4 * 4);
        __half h0, l0, h1, l1, h2, l2, h3, l3;
        split16(v.x, h0, l0); split16(v.y, h1, l1);
        split16(v.z, h2, l2); split16(v.w, h3, l3);
        __half2 hh01 = __halves2half2(h0, h1), hh23 = __halves2half2(h2, h3);
        __half2 ll01 = __halves2half2(l0, l1), ll23 = __halves2half2(l2, l3);
        uint2 hv, lv;
        hv.x = *(uint32_t*)&hh01; hv.y = *(uint32_t*)&hh23;
        lv.x = *(uint32_t*)&ll01; lv.y = *(uint32_t*)&ll23;
        *(uint2*)(smem + XA_HI + r * XROWB + i4 * 8) = hv;
        *(uint2*)(smem + XA_LO + r * XROWB + i4 * 8) = lv;
    }
    if (tid < 128) {
        int grow = R0 + tid;
        biasS[tid] = bias[((grow & 3) << 9) + (grow >> 2)];
    }
    __syncthreads();

    const int mi = wid;
    const uint32_t a_off = (uint32_t)(mi * 16 + (lane & 15)) * XROWB + ((lane >> 4) & 1) * 16;
    const int b_row = (lane & 7) + ((lane & 16) >> 1);
    const uint32_t b_off = (uint32_t)b_row * XROWB + ((lane >> 3) & 1) * 16;

    const int b_w  = tid >> 3;
    const int rq_w = tid & 7;

    for (int tl = 0; tl < 32; tl++) {
        const int t = t0 + tl;
        __syncthreads();

        // ---- stage x[t] hi/lo via cp.async from g_xh (pre-split)
        {
            #pragma unroll
            for (int j = 0; j < 8; j++) {
                int id  = tid + j * 256;      // 0..2047
                int op  = id >> 10;
                int rem = id & 1023;
                int b   = rem >> 5;
                int c   = rem & 31;           // 16B piece within row
                const __half* src = g_xh + (size_t)op * 4194304u
                                  + (((size_t)t * 32 + b) * 256) + c * 8;
                uint32_t dst = sb + (op ? XB_LO : XB_HI) + b * XROWB + c * 16;
                CP_ASYNC16(dst, src);
            }
            CP_COMMIT();
            CP_WAIT0();
        }
        __syncthreads();

        // ---- 3-pass MMA over K=256 (16 chunks)
        float accA[4][4], accB[4][4], accC[4][4];
        #pragma unroll
        for (int nt = 0; nt < 4; nt++)
            #pragma unroll
            for (int e = 0; e < 4; e++) { accA[nt][e] = 0.f; accB[nt][e] = 0.f; accC[nt][e] = 0.f; }

        {
            uint32_t aH = sb + XA_HI + a_off;
            uint32_t aL = sb + XA_LO + a_off;
            uint32_t bH0 = sb + XB_HI + b_off;
            uint32_t bH1 = bH0 + 16 * XROWB;
            uint32_t bL0 = sb + XB_LO + b_off;
            uint32_t bL1 = bL0 + 16 * XROWB;
            #pragma unroll 2
            for (int kc = 0; kc < 16; kc++) {
                uint32_t ahi[4], alo[4], bh[8], bl[8];
                ldm_x4(ahi[0], ahi[1], ahi[2], ahi[3], aH + kc * 32);
                ldm_x4(alo[0], alo[1], alo[2], alo[3], aL + kc * 32);
                ldm_x4(bh[0], bh[1], bh[2], bh[3], bH0 + kc * 32);
                ldm_x4(bh[4], bh[5], bh[6], bh[7], bH1 + kc * 32);
                ldm_x4(bl[0], bl[1], bl[2], bl[3], bL0 + kc * 32);
                ldm_x4(bl[4], bl[5], bl[6], bl[7], bL1 + kc * 32);
                #pragma unroll
                for (int nt = 0; nt < 4; nt++) {
                    mma16816(accA[nt], ahi, bh + nt * 2);
                    mma16816(accB[nt], ahi, bl + nt * 2);
                    mma16816(accC[nt], alo, bh + nt * 2);
                }
            }
        }

        // ---- dump D tile to Dst
        {
            int rw  = mi * 16 + (lane >> 2);
            int cw0 = (lane & 3) * 2;
            #pragma unroll
            for (int nt = 0; nt < 4; nt++) {
                int col = nt * 8 + cw0;
                Dst[rw * 33 + col]           = accA[nt][0] + accB[nt][0] + accC[nt][0];
                Dst[rw * 33 + col + 1]       = accA[nt][1] + accB[nt][1] + accC[nt][1];
                Dst[(rw + 8) * 33 + col]     = accA[nt][2] + accB[nt][2] + accC[nt][2];
                Dst[(rw + 8) * 33 + col + 1] = accA[nt][3] + accB[nt][3] + accC[nt][3];
            }
        }
        __syncthreads();

        // ---- write out with bias
        {
            float* op = g_xp + ((size_t)((d * 512 + t) * 32) + b_w) * 2048 + R0 + rq_w * 16;
            #pragma unroll
            for (int e = 0; e < 16; e += 4) {
                int r = rq_w * 16 + e;
                float4 o;
                o.x = Dst[(r + 0) * 33 + b_w] + biasS[r + 0];
                o.y = Dst[(r + 1) * 33 + b_w] + biasS[r + 1];
                o.z = Dst[(r + 2) * 33 + b_w] + biasS[r + 2];
                o.w = Dst[(r + 3) * 33 + b_w] + biasS[r + 3];
                *(float4*)(op + e) = o;
            }
        }
    }
}

// ==================================================================================
// Phase B: persistent recurrent kernel (v9.1: publish-first ordering).
// 128 CTAs x 256 thr, ~105KB smem, 1 CTA/SM, co-resident => spin-safe.
// Same proven v9 structure (A-in-registers, 2-pass, x4-B, per-lane flag gating).
// KEY CHANGE: flag release happens right after h-store + sync; the DRAM out-write
// and xp prefetch LDG are issued AFTER the release so they can no longer extend
// the inter-CTA critical path via release-store scoreboard draining.
// ==================================================================================
#define ROWB   1040
#define B_HI   0
#define B_LO   (B_HI + 32 * ROWB)
#define DST_O  (B_LO + 32 * ROWB)            // 66560 ; float[32*33] = 4224
#define AST_O  (DST_O + 4224)                // A staging (init only) 33280
#define RECUR_SMEM (AST_O + 33280)

__global__ __launch_bounds__(256, 1) void k_recur(
    const float* __restrict__ Whf,
    const float* __restrict__ Whb,
    float* __restrict__ out)
{
    extern __shared__ char smem[];
    const uint32_t sb = smem_to_u32(smem);
    float* Dst = (float*)(smem + DST_O);

    const int bid  = blockIdx.x;
    const int d    = bid >> 6;
    const int p    = bid & 63;
    const int j0   = p * 8;
    const int tid  = threadIdx.x;
    const int lane = tid & 31;
    const int wid  = tid >> 5;
    const int mi   = wid >> 2;           // 0..1  m-tile
    const int ni   = wid & 3;            // 0..3  n-tile
    const float* Wh = d ? Whb : Whf;

    // ---- stage W-hi rows (ju*4+g) into AST, then preload A fragments to registers
    for (int idx = tid; idx < 32 * 512; idx += 256) {
        int row = idx >> 9;
        int k   = idx & 511;
        int ju  = row >> 2, g = row & 3;
        float wv = Wh[((size_t)(g * 512 + j0 + ju)) * 512 + k];
        *(__half*)(smem + AST_O + row * ROWB + k * 2) = __float2half_rn(wv);
    }
    __syncthreads();

    uint32_t a_frag[32][4];
    {
        const uint32_t a_off = (uint32_t)(mi * 16 + (lane & 15)) * ROWB + ((lane >> 4) & 1) * 16;
        uint32_t aH = sb + AST_O + a_off;
        #pragma unroll
        for (int kc = 0; kc < 32; kc++)
            ldm_x4(a_frag[kc][0], a_frag[kc][1], a_frag[kc][2], a_frag[kc][3], aH + kc * 32);
    }
    __syncthreads();

    unsigned* flags  = g_flags + d * 64 * 32;
    unsigned* myflag = g_flags + (size_t)bid * 32;
    __half*   hsd    = g_hs + (size_t)d * 2 * 2 * 32 * 512;   // [parity][op][b][k]

    // B x4 lane offset: rows ni*8 + (lane&7); 16B col group (lane>>3)&3 spans 2 chunks
    const uint32_t b_off = (uint32_t)(ni * 8 + (lane & 7)) * ROWB + ((lane >> 3) & 3) * 16;

    const int ju_f = tid & 7;
    const int b_f  = tid >> 3;
    const int jg_f = j0 + ju_f;
    const int myprod = tid & 63;         // the producer this thread's staging depends on
    float c_st = 0.0f;

    float4 xg;
    {
        const int tt0 = d ? 511 : 0;
        xg = *(const float4*)(g_xp + ((size_t)((d * 512 + tt0) * 32) + b_f) * 2048 + jg_f * 4);
    }

    for (int s = 0; s < 512; s++) {
        const int tt = d ? (511 - s) : s;

        // ---- (0+1) per-lane gate + stage: poll ONLY my producer, then cp.async my 16
        while (ld_acquire_gpu(flags + myprod * 32) < (unsigned)s) { }
        {
            const uint4* hp = (const uint4*)(hsd + (size_t)(s & 1) * 2 * 32 * 512);
            #pragma unroll
            for (int i = 0; i < 16; i++) {
                int id  = tid + i * 256;
                int op  = id >> 11;
                int b   = (id >> 6) & 31;
                int k16 = id & 63;
                uint32_t daddr = sb + (op ? B_LO : B_HI) + b * ROWB + k16 * 16;
                CP_ASYNC16(daddr, hp + id);
            }
            CP_COMMIT();
            CP_WAIT0();
        }
        __syncthreads();

        // ---- (2) HMMA: 16 iter x (2 B-ldsm + 4 mma), A from registers
        float accA[4] = {0.f, 0.f, 0.f, 0.f};   // Whi * hhi
        float accB[4] = {0.f, 0.f, 0.f, 0.f};   // Whi * hlo
        {
            uint32_t bH = sb + B_HI + b_off;
            uint32_t bL = sb + B_LO + b_off;
            #pragma unroll 4
            for (int kc = 0; kc < 32; kc += 2) {
                uint32_t bh[4], bl[4];
                ldm_x4(bh[0], bh[1], bh[2], bh[3], bH + kc * 32);
                ldm_x4(bl[0], bl[1], bl[2], bl[3], bL + kc * 32);
                mma16816(accA, a_frag[kc],     bh);
                mma16816(accA, a_frag[kc + 1], bh + 2);
                mma16816(accB, a_frag[kc],     bl);
                mma16816(accB, a_frag[kc + 1], bl + 2);
            }
        }

        // ---- (3) dump D tile
        {
            int rw = mi * 16 + (lane >> 2);
            int cw = ni * 8 + (lane & 3) * 2;
            Dst[rw * 33 + cw]           = accA[0] + accB[0];
            Dst[rw * 33 + cw + 1]       = accA[1] + accB[1];
            Dst[(rw + 8) * 33 + cw]     = accA[2] + accB[2];
            Dst[(rw + 8) * 33 + cw + 1] = accA[3] + accB[3];
        }
        __syncthreads();

        // ---- (4) finalize + publish (critical path kept minimal)
        float h;
        {
            const float* db = Dst + (4 * ju_f) * 33 + b_f;
            float gi = sigmoid_t(db[0]  + xg.x);
            float gf = sigmoid_t(db[33] + xg.y);
            float gg = tanh_fast(db[66] + xg.z);
            float go = sigmoid_t(db[99] + xg.w);
            c_st = gf * c_st + gi * gg;
            h = go * tanh_fast(c_st);

            __half hi = __float2half_rn(h);
            __half lo = __float2half_rn(h - __half2float(hi));
            __half* hw = hsd + (size_t)((s + 1) & 1) * 2 * 32 * 512;
            hw[b_f * 512 + jg_f]         = hi;
            hw[16384 + b_f * 512 + jg_f] = lo;
        }
        __syncthreads();
        if (tid == 0) st_release_gpu(myflag, (unsigned)(s + 1));

        // ---- (5) non-critical tail: DRAM out-write + next-step xp prefetch
        out[((size_t)b_f * 512 + tt) * 1024 + d * 512 + jg_f] = h;
        if (s + 1 < 512) {
            const int ttn = d ? (510 - s) : (s + 1);
            xg = *(const float4*)(g_xp + ((size_t)((d * 512 + ttn) * 32) + b_f) * 2048 + jg_f * 4);
        }
    }
}

// ==================================================================================
extern "C" void kernel_launch(void* const* d_in, const int* in_sizes, int n_in,
                              void* d_out, int out_size)
{
    const float* x    = (const float*)d_in[0];
    const float* Wihf = (const float*)d_in[1];
    const float* Whhf = (const float*)d_in[2];
    const float* bf   = (const float*)d_in[3];
    const float* Wihb = (const float*)d_in[4];
    const float* Whhb = (const float*)d_in[5];
    const float* bb   = (const float*)d_in[6];
    float* out = (float*)d_out;

    cudaFuncSetAttribute(k_xproj, cudaFuncAttributeMaxDynamicSharedMemorySize, XPROJ_SMEM);
    cudaFuncSetAttribute(k_recur, cudaFuncAttributeMaxDynamicSharedMemorySize, RECUR_SMEM);

    k_xsplit<<<4096, 256>>>(x);
    k_xproj<<<dim3(16, 16, 2), 256, XPROJ_SMEM>>>(x, Wihf, bf, Wihb, bb);
    k_recur<<<128, 256, RECUR_SMEM>>>(Whhf, Whhb, out);
}

// round 15
// speedup vs baseline: 1.2679x; 1.1625x over previous
#include <cuda_runtime.h>
#include <cuda_fp16.h>
#include <cstdint>
#include <cstddef>

// Problem constants
#define NB 32
#define NT 512
#define NI 256
#define NH 512

// -------------------- device scratch (no allocations allowed) --------------------
// xp layout: [d][t][b(32)][row(2048)], row = unit*4 + gate  (gate: 0=i,1=f,2=g,3=o)
__device__ float    g_xp[2u * 512u * 32u * 2048u];   // 268 MB
// x pre-split fp16: [op(hi/lo)][t(512)][b(32)][i(256)]
__device__ __half   g_xh[2u * 512u * 32u * 256u];    // 16 MB
// h split-fp16 double buffer: [d][parity][op(hi/lo)][b(32)][k(512)] __half
__device__ __half   g_hs[2 * 2 * 2 * 32 * 512];
// per-producer step flags: flag[d][p] at stride 32 u32. 64 producers per dir.
__device__ unsigned g_flags[2 * 64 * 32];

// -------------------- helpers --------------------
__device__ __forceinline__ float tanh_fast(float x) {
    float r;
    asm("tanh.approx.f32 %0, %1;" : "=f"(r) : "f"(x));
    return r;
}
__device__ __forceinline__ float sigmoid_t(float x) {   // 0.5 + 0.5*tanh(x/2)
    return 0.5f + 0.5f * tanh_fast(0.5f * x);
}
__device__ __forceinline__ unsigned ld_acquire_gpu(const unsigned* p) {
    unsigned v;
    asm volatile("ld.acquire.gpu.u32 %0, [%1];" : "=r"(v) : "l"(p) : "memory");
    return v;
}
__device__ __forceinline__ void st_release_gpu(unsigned* p, unsigned v) {
    asm volatile("st.release.gpu.u32 [%0], %1;" :: "l"(p), "r"(v) : "memory");
}
__device__ __forceinline__ unsigned ld_acquire_sh(uint32_t addr) {
    unsigned v;
    asm volatile("ld.acquire.cta.shared.u32 %0, [%1];" : "=r"(v) : "r"(addr) : "memory");
    return v;
}
__device__ __forceinline__ void red_add_release_sh(uint32_t addr, unsigned v) {
    asm volatile("red.add.release.cta.shared.u32 [%0], %1;" :: "r"(addr), "r"(v) : "memory");
}
__device__ __forceinline__ uint32_t smem_to_u32(const void* smem_ptr) {
    uint32_t addr;
    asm("{ .reg .u64 tmp; cvta.to.shared.u64 tmp, %1; cvt.u32.u64 %0, tmp; }"
        : "=r"(addr) : "l"(smem_ptr));
    return addr;
}

// ldmatrix (sm_75+), mma.sync m16n8k16 f16->f32 (sm_80+), cp.async (sm_80+)
__device__ __forceinline__ void ldm_x4(uint32_t& r0, uint32_t& r1, uint32_t& r2, uint32_t& r3,
                                       uint32_t addr) {
    asm volatile("ldmatrix.sync.aligned.m8n8.x4.shared.b16 {%0,%1,%2,%3}, [%4];"
        : "=r"(r0), "=r"(r1), "=r"(r2), "=r"(r3) : "r"(addr));
}
__device__ __forceinline__ void mma16816(float* d, const uint32_t* a, const uint32_t* b) {
    asm volatile(
        "mma.sync.aligned.m16n8k16.row.col.f32.f16.f16.f32 "
        "{%0,%1,%2,%3}, {%4,%5,%6,%7}, {%8,%9}, {%0,%1,%2,%3};"
        : "+f"(d[0]), "+f"(d[1]), "+f"(d[2]), "+f"(d[3])
        : "r"(a[0]), "r"(a[1]), "r"(a[2]), "r"(a[3]), "r"(b[0]), "r"(b[1]));
}
#define CP_ASYNC16(smem_u32, gptr) \
    asm volatile("cp.async.cg.shared.global [%0], [%1], 16;" :: "r"(smem_u32), "l"(gptr))
#define CP_COMMIT()  asm volatile("cp.async.commit_group;" ::: "memory")
#define CP_WAIT0()   asm volatile("cp.async.wait_group 0;" ::: "memory")

// split a float into fp16 hi + fp16 lo
__device__ __forceinline__ void split16(float v, __half& hi, __half& lo) {
    hi = __float2half_rn(v);
    lo = __float2half_rn(v - __half2float(hi));
}

// ==================================================================================
// Phase A0: one-shot x split.  g_xh[op][t][b][i] = hi/lo fp16 of x[b][t][i].
// ==================================================================================
__global__ __launch_bounds__(256) void k_xsplit(const float* __restrict__ x) {
    int id = blockIdx.x * 256 + threadIdx.x;    // 0 .. 1048575
    int b   = id >> 15;
    int rem = id & 32767;
    int t   = rem >> 6;
    int i4  = rem & 63;
    float4 v = *(const float4*)(x + (size_t)id * 4);
    __half h0, l0, h1, l1, h2, l2, h3, l3;
    split16(v.x, h0, l0); split16(v.y, h1, l1);
    split16(v.z, h2, l2); split16(v.w, h3, l3);
    __half2 hh01 = __halves2half2(h0, h1), hh23 = __halves2half2(h2, h3);
    __half2 ll01 = __halves2half2(l0, l1), ll23 = __halves2half2(l2, l3);
    uint2 hv, lv;
    hv.x = *(uint32_t*)&hh01; hv.y = *(uint32_t*)&hh23;
    lv.x = *(uint32_t*)&ll01; lv.y = *(uint32_t*)&ll23;
    size_t dst = (((size_t)t * 32 + b) * 256) + i4 * 4;
    *(uint2*)(g_xh + dst)                     = hv;
    *(uint2*)(g_xh + 4194304u + dst)          = lv;   // op stride = 512*32*256
}

// ==================================================================================
// Phase A: HMMA input projections (3-pass split precision, proven in R11/R14).
// ==================================================================================
#define XROWB  528
#define XA_HI  0
#define XA_LO  (XA_HI + 128 * XROWB)
#define XB_HI  (XA_LO + 128 * XROWB)
#define XB_LO  (XB_HI + 32 * XROWB)
#define XDST   (XB_LO + 32 * XROWB)
#define XBIAS  (XDST + 16896)
#define XPROJ_SMEM (XBIAS + 640)

__global__ __launch_bounds__(256, 1) void k_xproj(
    const float* __restrict__ x,
    const float* __restrict__ Wf, const float* __restrict__ bf,
    const float* __restrict__ Wb, const float* __restrict__ bb)
{
    extern __shared__ char smem[];
    const uint32_t sb = smem_to_u32(smem);
    float* Dst   = (float*)(smem + XDST);
    float* biasS = (float*)(smem + XBIAS);

    const int d    = blockIdx.z;
    const int R0   = blockIdx.x * 128;
    const int t0   = blockIdx.y * 32;
    const int tid  = threadIdx.x;
    const int lane = tid & 31;
    const int wid  = tid >> 5;
    const float* W    = d ? Wb : Wf;
    const float* bias = d ? bb : bf;

    // ---- fused init: zero g_hs parity 0 (both dirs, hi+lo) + flags
    if (blockIdx.z == 0 && blockIdx.y == 0 && blockIdx.x < 8) {
        int t = blockIdx.x * 256 + tid;   // 0..2047
        #pragma unroll
        for (int r = 0; r < 4; r++) {
            int dd = r >> 1, op = r & 1;
            uint4* z = (uint4*)&g_hs[(((size_t)dd * 2 + 0) * 2 + op) * 32 * 512];
            z[t] = make_uint4(0, 0, 0, 0);
        }
        #pragma unroll
        for (int i = 0; i < 2; i++)
            g_flags[t + i * 2048] = 0u;
    }

    // ---- A stage: W rows hi/lo
    for (int idx = tid; idx < 8192; idx += 256) {
        int r  = idx >> 6;
        int i4 = idx & 63;
        int grow = R0 + r;
        int wrow = ((grow & 3) << 9) + (grow >> 2);
        float4 v = *(const float4*)(W + (size_t)wrow * 256 + i4 * 4);
        __half h0, l0, h1, l1, h2, l2, h3, l3;
        split16(v.x, h0, l0); split16(v.y, h1, l1);
        split16(v.z, h2, l2); split16(v.w, h3, l3);
        __half2 hh01 = __halves2half2(h0, h1), hh23 = __halves2half2(h2, h3);
        __half2 ll01 = __halves2half2(l0, l1), ll23 = __halves2half2(l2, l3);
        uint2 hv, lv;
        hv.x = *(uint32_t*)&hh01; hv.y = *(uint32_t*)&hh23;
        lv.x = *(uint32_t*)&ll01; lv.y = *(uint32_t*)&ll23;
        *(uint2*)(smem + XA_HI + r * XROWB + i4 * 8) = hv;
        *(uint2*)(smem + XA_LO + r * XROWB + i4 * 8) = lv;
    }
    if (tid < 128) {
        int grow = R0 + tid;
        biasS[tid] = bias[((grow & 3) << 9) + (grow >> 2)];
    }
    __syncthreads();

    const int mi = wid;
    const uint32_t a_off = (uint32_t)(mi * 16 + (lane & 15)) * XROWB + ((lane >> 4) & 1) * 16;
    const int b_row = (lane & 7) + ((lane & 16) >> 1);
    const uint32_t b_off = (uint32_t)b_row * XROWB + ((lane >> 3) & 1) * 16;

    const int b_w  = tid >> 3;
    const int rq_w = tid & 7;

    for (int tl = 0; tl < 32; tl++) {
        const int t = t0 + tl;
        __syncthreads();

        // ---- stage x[t] hi/lo via cp.async from g_xh (pre-split)
        {
            #pragma unroll
            for (int j = 0; j < 8; j++) {
                int id  = tid + j * 256;      // 0..2047
                int op  = id >> 10;
                int rem = id & 1023;
                int b   = rem >> 5;
                int c   = rem & 31;
                const __half* src = g_xh + (size_t)op * 4194304u
                                  + (((size_t)t * 32 + b) * 256) + c * 8;
                uint32_t dst = sb + (op ? XB_LO : XB_HI) + b * XROWB + c * 16;
                CP_ASYNC16(dst, src);
            }
            CP_COMMIT();
            CP_WAIT0();
        }
        __syncthreads();

        // ---- 3-pass MMA over K=256 (16 chunks)
        float accA[4][4], accB[4][4], accC[4][4];
        #pragma unroll
        for (int nt = 0; nt < 4; nt++)
            #pragma unroll
            for (int e = 0; e < 4; e++) { accA[nt][e] = 0.f; accB[nt][e] = 0.f; accC[nt][e] = 0.f; }

        {
            uint32_t aH = sb + XA_HI + a_off;
            uint32_t aL = sb + XA_LO + a_off;
            uint32_t bH0 = sb + XB_HI + b_off;
            uint32_t bH1 = bH0 + 16 * XROWB;
            uint32_t bL0 = sb + XB_LO + b_off;
            uint32_t bL1 = bL0 + 16 * XROWB;
            #pragma unroll 2
            for (int kc = 0; kc < 16; kc++) {
                uint32_t ahi[4], alo[4], bh[8], bl[8];
                ldm_x4(ahi[0], ahi[1], ahi[2], ahi[3], aH + kc * 32);
                ldm_x4(alo[0], alo[1], alo[2], alo[3], aL + kc * 32);
                ldm_x4(bh[0], bh[1], bh[2], bh[3], bH0 + kc * 32);
                ldm_x4(bh[4], bh[5], bh[6], bh[7], bH1 + kc * 32);
                ldm_x4(bl[0], bl[1], bl[2], bl[3], bL0 + kc * 32);
                ldm_x4(bl[4], bl[5], bl[6], bl[7], bL1 + kc * 32);
                #pragma unroll
                for (int nt = 0; nt < 4; nt++) {
                    mma16816(accA[nt], ahi, bh + nt * 2);
                    mma16816(accB[nt], ahi, bl + nt * 2);
                    mma16816(accC[nt], alo, bh + nt * 2);
                }
            }
        }

        // ---- dump D tile to Dst
        {
            int rw  = mi * 16 + (lane >> 2);
            int cw0 = (lane & 3) * 2;
            #pragma unroll
            for (int nt = 0; nt < 4; nt++) {
                int col = nt * 8 + cw0;
                Dst[rw * 33 + col]           = accA[nt][0] + accB[nt][0] + accC[nt][0];
                Dst[rw * 33 + col + 1]       = accA[nt][1] + accB[nt][1] + accC[nt][1];
                Dst[(rw + 8) * 33 + col]     = accA[nt][2] + accB[nt][2] + accC[nt][2];
                Dst[(rw + 8) * 33 + col + 1] = accA[nt][3] + accB[nt][3] + accC[nt][3];
            }
        }
        __syncthreads();

        // ---- write out with bias
        {
            float* op = g_xp + ((size_t)((d * 512 + t) * 32) + b_w) * 2048 + R0 + rq_w * 16;
            #pragma unroll
            for (int e = 0; e < 16; e += 4) {
                int r = rq_w * 16 + e;
                float4 o;
                o.x = Dst[(r + 0) * 33 + b_w] + biasS[r + 0];
                o.y = Dst[(r + 1) * 33 + b_w] + biasS[r + 1];
                o.z = Dst[(r + 2) * 33 + b_w] + biasS[r + 2];
                o.w = Dst[(r + 3) * 33 + b_w] + biasS[r + 3];
                *(float4*)(op + e) = o;
            }
        }
    }
}

// ==================================================================================
// Phase B: persistent recurrent kernel (v9.2: pipelined staging via group counters).
// 128 CTAs x 256 thr, ~106KB smem, 1 CTA/SM, co-resident => spin-safe.
// v9.1 structure + KEY CHANGE: the block-wide sync after staging is replaced by 4
// K-group readiness counters in smem. Thread tid stages only piece k16 = tid&63
// (= producer index); group g (producers 16g..16g+16) is ready when its 64 staging
// threads did cp.async+wait0+red.add.release(cnt[g]). Warps acquire-spin per group
// and MMA group g while later groups are still fetching (fetch/compute overlap).
// Counters accumulate 64/step (no reset; 512*64 << 2^31).
// Cross-step B reuse hazard: staging for s+1 happens only after that thread passed
// the release-sync of step s, which itself follows the Dst-dump sync => all warps
// finished reading step-s B.
// ==================================================================================
#define ROWB   1040
#define B_HI   0
#define B_LO   (B_HI + 32 * ROWB)
#define DST_O  (B_LO + 32 * ROWB)            // 66560 ; float[32*33] = 4224
#define CNT_O  (DST_O + 4224)                // 4 counters, stride 128B
#define AST_O  (CNT_O + 512)                 // A staging (init only) 33280
#define RECUR_SMEM (AST_O + 33280)

__global__ __launch_bounds__(256, 1) void k_recur(
    const float* __restrict__ Whf,
    const float* __restrict__ Whb,
    float* __restrict__ out)
{
    extern __shared__ char smem[];
    const uint32_t sb = smem_to_u32(smem);
    float* Dst = (float*)(smem + DST_O);

    const int bid  = blockIdx.x;
    const int d    = bid >> 6;
    const int p    = bid & 63;
    const int j0   = p * 8;
    const int tid  = threadIdx.x;
    const int lane = tid & 31;
    const int wid  = tid >> 5;
    const int mi   = wid >> 2;           // 0..1  m-tile
    const int ni   = wid & 3;            // 0..3  n-tile
    const float* Wh = d ? Whb : Whf;

    // ---- zero group counters
    if (tid < 4) *(unsigned*)(smem + CNT_O + tid * 128) = 0u;

    // ---- stage W-hi rows (ju*4+g) into AST, then preload A fragments to registers
    for (int idx = tid; idx < 32 * 512; idx += 256) {
        int row = idx >> 9;
        int k   = idx & 511;
        int ju  = row >> 2, g = row & 3;
        float wv = Wh[((size_t)(g * 512 + j0 + ju)) * 512 + k];
        *(__half*)(smem + AST_O + row * ROWB + k * 2) = __float2half_rn(wv);
    }
    __syncthreads();

    uint32_t a_frag[32][4];
    {
        const uint32_t a_off = (uint32_t)(mi * 16 + (lane & 15)) * ROWB + ((lane >> 4) & 1) * 16;
        uint32_t aH = sb + AST_O + a_off;
        #pragma unroll
        for (int kc = 0; kc < 32; kc++)
            ldm_x4(a_frag[kc][0], a_frag[kc][1], a_frag[kc][2], a_frag[kc][3], aH + kc * 32);
    }
    __syncthreads();

    unsigned* flags  = g_flags + d * 64 * 32;
    unsigned* myflag = g_flags + (size_t)bid * 32;
    __half*   hsd    = g_hs + (size_t)d * 2 * 2 * 32 * 512;   // [parity][op][b][k]

    // B x4 lane offset: rows ni*8 + (lane&7); 16B col group (lane>>3)&3 spans 2 chunks
    const uint32_t b_off = (uint32_t)(ni * 8 + (lane & 7)) * ROWB + ((lane >> 3) & 3) * 16;

    const int ju_f = tid & 7;
    const int b_f  = tid >> 3;
    const int jg_f = j0 + ju_f;
    const int myprod = tid & 63;               // piece/producer this thread stages
    const uint32_t mycnt = sb + CNT_O + (myprod >> 4) * 128;
    float c_st = 0.0f;

    float4 xg;
    {
        const int tt0 = d ? 511 : 0;
        xg = *(const float4*)(g_xp + ((size_t)((d * 512 + tt0) * 32) + b_f) * 2048 + jg_f * 4);
    }

    for (int s = 0; s < 512; s++) {
        const int tt = d ? (511 - s) : s;

        // ---- (1) stage: poll my producer, cp.async my 16 pieces, signal my group
        while (ld_acquire_gpu(flags + myprod * 32) < (unsigned)s) { }
        {
            const uint4* hp = (const uint4*)(hsd + (size_t)(s & 1) * 2 * 32 * 512);
            #pragma unroll
            for (int i = 0; i < 16; i++) {
                int id  = tid + i * 256;
                int op  = id >> 11;
                int b   = (id >> 6) & 31;
                int k16 = id & 63;
                uint32_t daddr = sb + (op ? B_LO : B_HI) + b * ROWB + k16 * 16;
                CP_ASYNC16(daddr, hp + id);
            }
            CP_COMMIT();
            CP_WAIT0();
            red_add_release_sh(mycnt, 1u);
        }

        // ---- (2) HMMA, pipelined per K-group: spin group counter, then 4 iters
        float accA[4] = {0.f, 0.f, 0.f, 0.f};   // Whi * hhi
        float accB[4] = {0.f, 0.f, 0.f, 0.f};   // Whi * hlo
        {
            uint32_t bH = sb + B_HI + b_off;
            uint32_t bL = sb + B_LO + b_off;
            const unsigned tgt = 64u * (unsigned)(s + 1);
            #pragma unroll
            for (int g = 0; g < 4; g++) {
                while (ld_acquire_sh(sb + CNT_O + g * 128) < tgt) { }
                #pragma unroll
                for (int kc = 8 * g; kc < 8 * g + 8; kc += 2) {
                    uint32_t bh[4], bl[4];
                    ldm_x4(bh[0], bh[1], bh[2], bh[3], bH + kc * 32);
                    ldm_x4(bl[0], bl[1], bl[2], bl[3], bL + kc * 32);
                    mma16816(accA, a_frag[kc],     bh);
                    mma16816(accA, a_frag[kc + 1], bh + 2);
                    mma16816(accB, a_frag[kc],     bl);
                    mma16816(accB, a_frag[kc + 1], bl + 2);
                }
            }
        }

        // ---- (3) dump D tile
        {
            int rw = mi * 16 + (lane >> 2);
            int cw = ni * 8 + (lane & 3) * 2;
            Dst[rw * 33 + cw]           = accA[0] + accB[0];
            Dst[rw * 33 + cw + 1]       = accA[1] + accB[1];
            Dst[(rw + 8) * 33 + cw]     = accA[2] + accB[2];
            Dst[(rw + 8) * 33 + cw + 1] = accA[3] + accB[3];
        }
        __syncthreads();

        // ---- (4) finalize + publish (critical path kept minimal)
        float h;
        {
            const float* db = Dst + (4 * ju_f) * 33 + b_f;
            float gi = sigmoid_t(db[0]  + xg.x);
            float gf = sigmoid_t(db[33] + xg.y);
            float gg = tanh_fast(db[66] + xg.z);
            float go = sigmoid_t(db[99] + xg.w);
            c_st = gf * c_st + gi * gg;
            h = go * tanh_fast(c_st);

            __half hi = __float2half_rn(h);
            __half lo = __float2half_rn(h - __half2float(hi));
            __half* hw = hsd + (size_t)((s + 1) & 1) * 2 * 32 * 512;
            hw[b_f * 512 + jg_f]         = hi;
            hw[16384 + b_f * 512 + jg_f] = lo;
        }
        __syncthreads();
        if (tid == 0) st_release_gpu(myflag, (unsigned)(s + 1));

        // ---- (5) non-critical tail: DRAM out-write + next-step xp prefetch
        out[((size_t)b_f * 512 + tt) * 1024 + d * 512 + jg_f] = h;
        if (s + 1 < 512) {
            const int ttn = d ? (510 - s) : (s + 1);
            xg = *(const float4*)(g_xp + ((size_t)((d * 512 + ttn) * 32) + b_f) * 2048 + jg_f * 4);
        }
    }
}

// ==================================================================================
extern "C" void kernel_launch(void* const* d_in, const int* in_sizes, int n_in,
                              void* d_out, int out_size)
{
    const float* x    = (const float*)d_in[0];
    const float* Wihf = (const float*)d_in[1];
    const float* Whhf = (const float*)d_in[2];
    const float* bf   = (const float*)d_in[3];
    const float* Wihb = (const float*)d_in[4];
    const float* Whhb = (const float*)d_in[5];
    const float* bb   = (const float*)d_in[6];
    float* out = (float*)d_out;

    cudaFuncSetAttribute(k_xproj, cudaFuncAttributeMaxDynamicSharedMemorySize, XPROJ_SMEM);
    cudaFuncSetAttribute(k_recur, cudaFuncAttributeMaxDynamicSharedMemorySize, RECUR_SMEM);

    k_xsplit<<<4096, 256>>>(x);
    k_xproj<<<dim3(16, 16, 2), 256, XPROJ_SMEM>>>(x, Wihf, bf, Wihb, bb);
    k_recur<<<128, 256, RECUR_SMEM>>>(Whhf, Whhb, out);
}